// round 15
// baseline (speedup 1.0000x reference)
#include <cuda_runtime.h>
#include <math.h>

// Problem constants (fixed by the reference)
#define NN    1536   // nodes
#define DEG   32     // candidate out-degree per node
#define BS    8      // sequential batch steps
#define OBSD  33
#define HIDN  64
#define NH    4      // heads
#define CD    8      // channels per head
#define KS    4      // top-k
#define EMB   32
#define ATTN_OFS ((size_t)BS * NN * EMB)   // outs precede attns in d_out

#define PNT 32   // (t,node) pairs per block in post (4 groups x 8)
#define K2W 4    // warps per block in k2

// -------- persistent device scratch (no allocations allowed) --------
__device__ float g_WihT[EMB * 3 * HIDN];     // transposed Wih: [k][o]
__device__ float g_gi[BS * NN * 3 * HIDN];   // input-side GRU gates (batched)
__device__ float g_hall[BS * NN * HIDN];
__device__ float g_P[BS * NN * HIDN];
__device__ float g_Q[BS * NN * HIDN];
__device__ float g_xh[BS * NN * EMB];
__device__ float g_as[BS * NN * NH];
__device__ float g_ad[BS * NN * NH];
__device__ int   g_kdst[BS * NN * KS];
__device__ float g_kw[BS * NN * KS];
__device__ float g_kex[BS * NN * KS * NH];
__device__ float g_ssum[BS * NN * NH];
__device__ float g_Aval[BS * NN * KS * NH];  // normalized, dedup-merged A entries
__device__ int   g_Adst[BS * NN * KS];       // -1 = duplicate slot (skip)

__device__ __forceinline__ float sigm(float x) { return 1.f / (1.f + expf(-x)); }

// ---------------- zero-fill the whole attention output region (DRAM-floor kernel) ----------------
__global__ void zeroA(float* __restrict__ outp) {
    float4* base = (float4*)(outp + ATTN_OFS);
    size_t total = (size_t)BS * NH * NN * NN / 4;
    size_t stride = (size_t)gridDim.x * blockDim.x;
    float4 z = make_float4(0.f, 0.f, 0.f, 0.f);
    for (size_t i = (size_t)blockIdx.x * blockDim.x + threadIdx.x; i < total; i += stride)
        base[i] = z;
}

// ---------------- transWih: Wih[o][k] -> WihT[k][o] (one-time, tiny) ----------------
__global__ void transWih(const float* __restrict__ Wih) {
    int i = blockIdx.x * 256 + threadIdx.x;      // 6144 elements
    if (i < 3 * HIDN * EMB) {
        int o = i >> 5, k = i & 31;
        g_WihT[k * (3 * HIDN) + o] = Wih[i];
    }
}

// ---------------- emb_gi: ObsEmbedding + input-side GRU gates, FUSED ----------------
// grid = BS*NN/8 = 1536 blocks, 256 threads; warp w owns row r = blk*8+w entirely.
// Embedding body identical to the verified embed_k math (warp-per-row). gi uses the
// TRANSPOSED WihT so each (k,i) weight read is lane-coalesced (no gathers).
__global__ void __launch_bounds__(256, 6)
emb_gi(const float* __restrict__ Ht,
       const float* __restrict__ We1, const float* __restrict__ be1,
       const float* __restrict__ We2, const float* __restrict__ be2,
       const float* __restrict__ lng, const float* __restrict__ lnb,
       const float* __restrict__ bih) {
    int w = threadIdx.x >> 5, j = threadIdx.x & 31;
    size_t r = (size_t)blockIdx.x * 8 + w;       // flat (t*NN + n)
    __shared__ float in_s[8][OBSD + 3];
    __shared__ float e_s[8][EMB];

    const float* row = Ht + r * OBSD;
    in_s[w][j] = row[j];
    if (j == 0) in_s[w][32] = row[32];
    __syncwarp();

    float a = be1[j];
#pragma unroll
    for (int k = 0; k < OBSD; k++) a += in_s[w][k] * We1[k * EMB + j];
    a = fmaxf(a, 0.f);
    in_s[w][j] = a;   // reuse as x1
    __syncwarp();

    float b = be2[j];
#pragma unroll
    for (int k = 0; k < EMB; k++) b += in_s[w][k] * We2[k * EMB + j];
    float x = fmaxf(b, 0.f);

    // LayerNorm over 32 (one warp per row)
    float s = x;
#pragma unroll
    for (int o = 16; o; o >>= 1) s += __shfl_xor_sync(0xffffffffu, s, o);
    float mu = s * (1.f / 32.f);
    float d  = x - mu;
    float v  = d * d;
#pragma unroll
    for (int o = 16; o; o >>= 1) v += __shfl_xor_sync(0xffffffffu, v, o);
    float e = d * rsqrtf(v * (1.f / 32.f) + 1e-5f) * lng[j] + lnb[j];
    e_s[w][j] = e;
    __syncwarp();

    // gi[o] = bih[o] + sum_k e[k] * WihT[k][o]; lane j computes o = j + 32*i
    float* go = g_gi + r * 192;
    float acc[6];
#pragma unroll
    for (int i = 0; i < 6; i++) acc[i] = bih[j + 32 * i];
#pragma unroll
    for (int k = 0; k < EMB; k++) {
        float ev = e_s[w][k];
        const float* wr = g_WihT + k * 192 + j;
#pragma unroll
        for (int i = 0; i < 6; i++) acc[i] += ev * wr[32 * i];   // lane-coalesced
    }
#pragma unroll
    for (int i = 0; i < 6; i++) go[j + 32 * i] = acc[i];
}

// ---------------- gruAll: 8 GRU steps, one node/block, k4-split (R14 verified) ----------------
__global__ void __launch_bounds__(256, 3)
gruAll(const float* __restrict__ Whh, const float* __restrict__ bhh) {
    __shared__ float h_s[HIDN];
    __shared__ float a_s[3][HIDN];
    const unsigned full = 0xffffffffu;
    int tid = threadIdx.x;
    int lane = tid & 31, w = tid >> 5;
    int k4 = lane & 3, jq = lane >> 2;
    int j  = w * 8 + jq;
    int kb = k4 * 16;
    int n  = blockIdx.x;

    // weight registers: 3 gate rows x 16 consecutive k
    const float4* p0 = (const float4*)(Whh + (size_t)j * HIDN + kb);
    const float4* p1 = (const float4*)(Whh + (size_t)(HIDN + j) * HIDN + kb);
    const float4* p2 = (const float4*)(Whh + (size_t)(2 * HIDN + j) * HIDN + kb);
    float4 w0a = p0[0], w0b = p0[1], w0c = p0[2], w0d = p0[3];
    float4 w1a = p1[0], w1b = p1[1], w1c = p1[2], w1d = p1[3];
    float4 w2a = p2[0], w2b = p2[1], w2c = p2[2], w2d = p2[3];
    float b0 = bhh[j], b1 = bhh[HIDN + j], b2 = bhh[2 * HIDN + j];

    // activation-thread state (threads 0..63): prefetch gi for step 0
    float gp0 = 0.f, gp1 = 0.f, gp2 = 0.f;
    if (tid < HIDN) {
        h_s[tid] = 0.f;
        size_t gb = (size_t)n * 192;
        gp0 = g_gi[gb + tid];
        gp1 = g_gi[gb + HIDN + tid];
        gp2 = g_gi[gb + 2 * HIDN + tid];
    }
    __syncthreads();

    for (int t = 0; t < BS; t++) {
        // ---- FMA phase (all 8 warps) ----
        float4 hA = *(const float4*)(h_s + kb);
        float4 hB = *(const float4*)(h_s + kb + 4);
        float4 hC = *(const float4*)(h_s + kb + 8);
        float4 hD = *(const float4*)(h_s + kb + 12);
        float a0 = hA.x * w0a.x + hA.y * w0a.y + hA.z * w0a.z + hA.w * w0a.w
                 + hB.x * w0b.x + hB.y * w0b.y + hB.z * w0b.z + hB.w * w0b.w
                 + hC.x * w0c.x + hC.y * w0c.y + hC.z * w0c.z + hC.w * w0c.w
                 + hD.x * w0d.x + hD.y * w0d.y + hD.z * w0d.z + hD.w * w0d.w;
        float a1 = hA.x * w1a.x + hA.y * w1a.y + hA.z * w1a.z + hA.w * w1a.w
                 + hB.x * w1b.x + hB.y * w1b.y + hB.z * w1b.z + hB.w * w1b.w
                 + hC.x * w1c.x + hC.y * w1c.y + hC.z * w1c.z + hC.w * w1c.w
                 + hD.x * w1d.x + hD.y * w1d.y + hD.z * w1d.z + hD.w * w1d.w;
        float a2 = hA.x * w2a.x + hA.y * w2a.y + hA.z * w2a.z + hA.w * w2a.w
                 + hB.x * w2b.x + hB.y * w2b.y + hB.z * w2b.z + hB.w * w2b.w
                 + hC.x * w2c.x + hC.y * w2c.y + hC.z * w2c.z + hC.w * w2c.w
                 + hD.x * w2d.x + hD.y * w2d.y + hD.z * w2d.z + hD.w * w2d.w;
#pragma unroll
        for (int o = 2; o; o >>= 1) {
            a0 += __shfl_xor_sync(full, a0, o);
            a1 += __shfl_xor_sync(full, a1, o);
            a2 += __shfl_xor_sync(full, a2, o);
        }
        if (k4 == 0) {
            a_s[0][j] = a0 + b0;
            a_s[1][j] = a1 + b1;
            a_s[2][j] = a2 + b2;
        }
        __syncthreads();

        // ---- activation phase (2 dense warps) ----
        if (tid < HIDN) {
            int u = tid;
            float r  = sigm(gp0 + a_s[0][u]);
            float z  = sigm(gp1 + a_s[1][u]);
            float nv = tanhf(gp2 + a_s[2][u] * r);
            float hn = (1.f - z) * nv + z * h_s[u];
            h_s[u] = hn;
            g_hall[((size_t)t * NN + n) * HIDN + u] = hn;
            if (t < BS - 1) {
                size_t gb = ((size_t)(t + 1) * NN + n) * 192;
                gp0 = g_gi[gb + u];
                gp1 = g_gi[gb + HIDN + u];
                gp2 = g_gi[gb + 2 * HIDN + u];
            }
        }
        __syncthreads();
    }
}

// ---------------- post_all: P/Q/xh/a_s/a_d + inits; NO weight staging (occupancy fix) ----------------
// Ws1[k*64+j] reads are already lane-coalesced and L1-resident (32KB). smem 12KB ->
// 6 blocks/SM instead of 4, one less barrier.
__global__ void __launch_bounds__(256, 6)
post_k(const float* __restrict__ Ws1, const float* __restrict__ bs1,
       const float* __restrict__ Wgat,
       const float* __restrict__ asrc, const float* __restrict__ adst,
       const float* __restrict__ bgat,
       float* __restrict__ outp) {
    size_t r0 = (size_t)blockIdx.x * PNT;   // flat (t*NN+n) index
    int tid = threadIdx.x;
    int s = tid >> 6, j = tid & 63;
    __shared__ float hn_s[PNT][HIDN];          // 8 KB
    __shared__ float xh_s[PNT][EMB];           // 4 KB

    for (int i = tid; i < PNT * HIDN; i += 256)
        hn_s[i >> 6][i & 63] = g_hall[r0 * HIDN + i];
    __syncthreads();

    const int mb = s * 8;  // row base for this group
    float p[8], q[8];
    float bp = bs1[j];
#pragma unroll
    for (int m = 0; m < 8; m++) { p[m] = bp; q[m] = 0.f; }
#pragma unroll 8
    for (int k = 0; k < HIDN; k++) {
        float w1 = Ws1[k * HIDN + j];              // coalesced, L1-resident
        float w2 = Ws1[(HIDN + k) * HIDN + j];
#pragma unroll
        for (int m = 0; m < 8; m++) {
            float h = hn_s[mb + m][k];
            p[m] += h * w1; q[m] += h * w2;
        }
    }
#pragma unroll
    for (int m = 0; m < 8; m++) {
        g_P[(r0 + mb + m) * HIDN + j] = p[m];
        g_Q[(r0 + mb + m) * HIDN + j] = q[m];
    }

    if (j < EMB) {
        float x[8];
#pragma unroll
        for (int m = 0; m < 8; m++) x[m] = 0.f;
#pragma unroll 8
        for (int k = 0; k < HIDN; k++) {
            float w = Wgat[k * EMB + j];
#pragma unroll
            for (int m = 0; m < 8; m++) x[m] += hn_s[mb + m][k] * w;
        }
        float bg = bgat[j];
#pragma unroll
        for (int m = 0; m < 8; m++) {
            xh_s[mb + m][j] = x[m];
            g_xh[(r0 + mb + m) * EMB + j] = x[m];
            outp[(r0 + mb + m) * EMB + j] = bg;  // segment_sum init + bias
        }
    }
    __syncthreads();

    if (j < 8 * NH) {
        int m = mb + (j >> 2), h = j & 3;
        float as_ = 0.f, ad_ = 0.f;
#pragma unroll
        for (int c = 0; c < CD; c++) {
            as_ += xh_s[m][h * CD + c] * asrc[h * CD + c];
            ad_ += xh_s[m][h * CD + c] * adst[h * CD + c];
        }
        g_as[(r0 + m) * NH + h]   = as_;
        g_ad[(r0 + m) * NH + h]   = ad_;
        g_ssum[(r0 + m) * NH + h] = 0.f;
    }
}

// ---------------- k2_all: edge scores with COALESCED Q staging (verified R13) ----------------
__global__ void __launch_bounds__(128, 6)
k2_all(const int* __restrict__ dst,
       const float* __restrict__ Ws2, const float* __restrict__ bs2) {
    const unsigned full = 0xffffffffu;
    int warp = threadIdx.x >> 5, lane = threadIdx.x & 31;
    size_t b = (size_t)blockIdx.x * K2W + warp;   // flat (t*NN + n)
    int n = (int)(b % NN);
    size_t tbase = b - n;                          // t*NN

    __shared__ float w2_s[HIDN];
    __shared__ float P_sh[K2W][HIDN];
    __shared__ __align__(16) float q_s[K2W][DEG][68];
    if (threadIdx.x < HIDN) w2_s[threadIdx.x] = Ws2[threadIdx.x];
    P_sh[warp][lane]      = g_P[b * HIDN + lane];
    P_sh[warp][32 + lane] = g_P[b * HIDN + 32 + lane];
    float as0 = g_as[b * NH + 0], as1 = g_as[b * NH + 1];
    float as2 = g_as[b * NH + 2], as3 = g_as[b * NH + 3];
    __syncthreads();

    int d = dst[n * DEG + lane];

    // coalesced staging: row-by-row, float2 per lane
#pragma unroll 8
    for (int r = 0; r < DEG; r++) {
        int dr = __shfl_sync(full, d, r);
        float2 qv = *(const float2*)(g_Q + (tbase + dr) * HIDN + lane * 2);
        *(float2*)(&q_s[warp][r][lane * 2]) = qv;
    }
    __syncwarp();

    // dot over own row (same k-ascending float4 sequence as the verified gather kernel)
    const float* qq = q_s[warp][lane];
    const float* P_s = P_sh[warp];
    float acc = bs2[0];
#pragma unroll
    for (int k4 = 0; k4 < HIDN / 4; k4++) {
        float4 qv = *(const float4*)(qq + k4 * 4);
        int k = k4 * 4;
        acc += fmaxf(P_s[k] + qv.x, 0.f) * w2_s[k]
             + fmaxf(P_s[k + 1] + qv.y, 0.f) * w2_s[k + 1]
             + fmaxf(P_s[k + 2] + qv.z, 0.f) * w2_s[k + 2]
             + fmaxf(P_s[k + 3] + qv.w, 0.f) * w2_s[k + 3];
    }
    float score = sigm(acc);

    // top-k (k=4) among 32 lanes; ties -> lower index (matches jax.lax.top_k)
    bool sel = false;
#pragma unroll
    for (int r = 0; r < KS; r++) {
        float v = sel ? -1e30f : score;
        int   idx = lane;
#pragma unroll
        for (int o = 16; o; o >>= 1) {
            float ov = __shfl_xor_sync(full, v, o);
            int   oi = __shfl_xor_sync(full, idx, o);
            if (ov > v || (ov == v && oi < idx)) { v = ov; idx = oi; }
        }
        if (lane == idx) sel = true;
    }
    unsigned ball = __ballot_sync(full, sel);
    if (sel) {
        int slot = __popc(ball & ((1u << lane) - 1u));
        g_kdst[b * KS + slot] = d;
        g_kw[b * KS + slot]   = score;
        float4 adv = *(const float4*)(g_ad + (tbase + d) * NH);
        float4 ex4;
        float lg;
        lg = as0 + adv.x; lg = lg > 0.f ? lg : 0.2f * lg; ex4.x = expf(lg);
        lg = as1 + adv.y; lg = lg > 0.f ? lg : 0.2f * lg; ex4.y = expf(lg);
        lg = as2 + adv.z; lg = lg > 0.f ? lg : 0.2f * lg; ex4.z = expf(lg);
        lg = as3 + adv.w; lg = lg > 0.f ? lg : 0.2f * lg; ex4.w = expf(lg);
        *(float4*)(g_kex + (b * KS + slot) * NH) = ex4;
        float* ss = g_ssum + (tbase + d) * NH;
        atomicAdd(ss + 0, ex4.x);
        atomicAdd(ss + 1, ex4.y);
        atomicAdd(ss + 2, ex4.z);
        atomicAdd(ss + 3, ex4.w);
    }
}

// ---------------- k4_all: alpha + row-normalize + dedup + out messages ----------------
__global__ void __launch_bounds__(256, 8)
k4_all(float* __restrict__ outp) {
    int warp = threadIdx.x >> 5, lane = threadIdx.x & 31;
    size_t b = (size_t)blockIdx.x * 8 + warp;   // flat (t*NN + n)
    int n = (int)(b % NN);
    size_t tbase = b - n;                        // t*NN
    const unsigned full = 0xffffffffu;
    int i = (lane >> 2) & 3, h = lane & 3;       // lanes 16..31 mirror 0..15

    int   d_i = g_kdst[b * KS + i];
    float w_i = g_kw[b * KS + i];
    float ex  = g_kex[(b * KS + i) * NH + h];
    float alpha = ex / fmaxf(g_ssum[(tbase + d_i) * NH + h], 1e-16f);

    float rs = alpha;
    rs += __shfl_xor_sync(full, rs, 4);
    rs += __shfl_xor_sync(full, rs, 8);
    float rinv = 1.f / fmaxf(rs, 1e-9f);

    bool first = true;
    float acc = alpha;
#pragma unroll
    for (int jj = 0; jj < KS; jj++) {
        int   dj = __shfl_sync(full, d_i,   jj * 4 + h);
        float aj = __shfl_sync(full, alpha, jj * 4 + h);
        if (jj < i && dj == d_i) first = false;
        if (jj > i && dj == d_i) acc += aj;
    }
    if (lane < 16) {
        g_Aval[(b * KS + i) * NH + h] = first ? acc * rinv : 0.f;
        if (h == 0) g_Adst[b * KS + i] = first ? d_i : -1;
    }

    int h2 = lane >> 3, c = lane & 7;
    float xhv = g_xh[b * EMB + h2 * CD + c];
#pragma unroll
    for (int jj = 0; jj < KS; jj++) {
        float a_jh = __shfl_sync(full, alpha, jj * 4 + h2);
        float wj   = __shfl_sync(full, w_i,   jj * 4);
        int   dj   = __shfl_sync(full, d_i,   jj * 4);
        atomicAdd(&outp[(tbase + dj) * EMB + h2 * CD + c], a_jh * xhv * wj);
    }
}

// ---------------- scatterA: write the nonzero attention entries ----------------
__global__ void scatterA(float* __restrict__ outp) {
    int gid = blockIdx.x * blockDim.x + threadIdx.x;
    if (gid >= BS * NN * KS) return;
    int slot = gid & 3;
    size_t b = gid >> 2;          // t*NN + n
    int n = (int)(b % NN);
    int t = (int)(b / NN);
    int d = g_Adst[b * KS + slot];
    if (d < 0) return;
    float4 v = *(const float4*)(g_Aval + (b * KS + slot) * NH);
    float* Abase = outp + ATTN_OFS;
    size_t rowstride = (size_t)NN * NN;
    size_t base = ((size_t)t * NH) * rowstride + (size_t)n * NN + d;
    Abase[base]                 = v.x;
    Abase[base + rowstride]     = v.y;
    Abase[base + 2 * rowstride] = v.z;
    Abase[base + 3 * rowstride] = v.w;
}

// ---------------- launch (single stream) ----------------
extern "C" void kernel_launch(void* const* d_in, const int* in_sizes, int n_in,
                              void* d_out, int out_size) {
    int base = (in_sizes[3] == 1) ? 4 : 3;  // scalar k may or may not be materialized
    const float* Ht  = (const float*)d_in[0];
    const int*   dst = (const int*)d_in[2];
    const float* We1 = (const float*)d_in[base + 0];
    const float* be1 = (const float*)d_in[base + 1];
    const float* We2 = (const float*)d_in[base + 2];
    const float* be2 = (const float*)d_in[base + 3];
    const float* lng = (const float*)d_in[base + 4];
    const float* lnb = (const float*)d_in[base + 5];
    const float* Wih = (const float*)d_in[base + 6];
    const float* Whh = (const float*)d_in[base + 7];
    const float* bih = (const float*)d_in[base + 8];
    const float* bhh = (const float*)d_in[base + 9];
    const float* Ws1 = (const float*)d_in[base + 10];
    const float* bs1 = (const float*)d_in[base + 11];
    const float* Ws2 = (const float*)d_in[base + 12];
    const float* bs2 = (const float*)d_in[base + 13];
    const float* Wgat = (const float*)d_in[base + 14];
    const float* asrc = (const float*)d_in[base + 15];
    const float* adst = (const float*)d_in[base + 16];
    const float* bgat = (const float*)d_in[base + 17];
    float* outp = (float*)d_out;

    zeroA<<<4608, 256>>>(outp);
    transWih<<<(3 * HIDN * EMB + 255) / 256, 256>>>(Wih);
    emb_gi<<<(BS * NN) / 8, 256>>>(Ht, We1, be1, We2, be2, lng, lnb, bih);
    gruAll<<<NN, 256>>>(Whh, bhh);
    post_k<<<(BS * NN) / PNT, 256>>>(Ws1, bs1, Wgat, asrc, adst, bgat, outp);
    k2_all<<<(BS * NN) / K2W, 128>>>(dst, Ws2, bs2);
    k4_all<<<(BS * NN) / 8, 256>>>(outp);
    scatterA<<<(BS * NN * KS + 255) / 256, 256>>>(outp);
}

// round 16
// speedup vs baseline: 1.1768x; 1.1768x over previous
#include <cuda_runtime.h>
#include <math.h>

// Problem constants (fixed by the reference)
#define NN    1536   // nodes
#define DEG   32     // candidate out-degree per node
#define BS    8      // sequential batch steps
#define OBSD  33
#define HIDN  64
#define NH    4      // heads
#define CD    8      // channels per head
#define KS    4      // top-k
#define EMB   32
#define ATTN_OFS ((size_t)BS * NN * EMB)   // outs precede attns in d_out

#define RTB 8    // rows per block in embed
#define INT 8    // rows per block in gi_all
#define PNT 32   // (t,node) pairs per block in post (4 groups x 8)
#define K2W 4    // warps per block in k2

// -------- persistent device scratch (no allocations allowed) --------
__device__ float g_Hemb[BS * NN * EMB];
__device__ float g_WihT[EMB * 3 * HIDN];     // transposed Wih: [k][o]
__device__ float g_gi[BS * NN * 3 * HIDN];   // input-side GRU gates (batched)
__device__ float g_hall[BS * NN * HIDN];
__device__ float g_P[BS * NN * HIDN];
__device__ float g_Q[BS * NN * HIDN];
__device__ float g_xh[BS * NN * EMB];
__device__ float g_as[BS * NN * NH];
__device__ float g_ad[BS * NN * NH];
__device__ int   g_kdst[BS * NN * KS];
__device__ float g_kw[BS * NN * KS];
__device__ float g_kex[BS * NN * KS * NH];
__device__ float g_ssum[BS * NN * NH];
__device__ float g_Aval[BS * NN * KS * NH];  // normalized, dedup-merged A entries
__device__ int   g_Adst[BS * NN * KS];       // -1 = duplicate slot (skip)

__device__ __forceinline__ float sigm(float x) { return 1.f / (1.f + expf(-x)); }

// ---------------- zero-fill the whole attention output region (DRAM-floor kernel) ----------------
__global__ void zeroA(float* __restrict__ outp) {
    float4* base = (float4*)(outp + ATTN_OFS);
    size_t total = (size_t)BS * NH * NN * NN / 4;
    size_t stride = (size_t)gridDim.x * blockDim.x;
    float4 z = make_float4(0.f, 0.f, 0.f, 0.f);
    for (size_t i = (size_t)blockIdx.x * blockDim.x + threadIdx.x; i < total; i += stride)
        base[i] = z;
}

// ---------------- transWih: Wih[o][k] -> WihT[k][o] (one-time, tiny) ----------------
__global__ void transWih(const float* __restrict__ Wih) {
    int i = blockIdx.x * 256 + threadIdx.x;      // 6144 elements
    if (i < 3 * HIDN * EMB) {
        int o = i >> 5, k = i & 31;
        g_WihT[k * (3 * HIDN) + o] = Wih[i];
    }
}

// ---------------- Obs embedding: Linear-ReLU-Linear-ReLU-LayerNorm (R14 verified) ----------------
__global__ void __launch_bounds__(32, 16)
embed_k(const float* __restrict__ Ht,
        const float* __restrict__ We1, const float* __restrict__ be1,
        const float* __restrict__ We2, const float* __restrict__ be2,
        const float* __restrict__ lng, const float* __restrict__ lnb) {
    int r0 = blockIdx.x * RTB;
    int j  = threadIdx.x;  // 0..31
    __shared__ float in_s[RTB][OBSD + 1];
    __shared__ float x1_s[RTB][EMB];

    for (int t = j; t < RTB * OBSD; t += 32)
        in_s[t / OBSD][t % OBSD] = Ht[(size_t)r0 * OBSD + t];
    __syncwarp();

    float a[RTB];
    float b1 = be1[j];
#pragma unroll
    for (int m = 0; m < RTB; m++) a[m] = b1;
#pragma unroll
    for (int k = 0; k < OBSD; k++) {
        float w = We1[k * EMB + j];
#pragma unroll
        for (int m = 0; m < RTB; m++) a[m] += in_s[m][k] * w;
    }
#pragma unroll
    for (int m = 0; m < RTB; m++) x1_s[m][j] = fmaxf(a[m], 0.f);
    __syncwarp();

    float b[RTB];
    float b2 = be2[j];
#pragma unroll
    for (int m = 0; m < RTB; m++) b[m] = b2;
#pragma unroll
    for (int k = 0; k < EMB; k++) {
        float w = We2[k * EMB + j];
#pragma unroll
        for (int m = 0; m < RTB; m++) b[m] += x1_s[m][k] * w;
    }

    float gj = lng[j], bj = lnb[j];
#pragma unroll
    for (int m = 0; m < RTB; m++) {
        float x = fmaxf(b[m], 0.f);
        float s = x;
#pragma unroll
        for (int o = 16; o; o >>= 1) s += __shfl_xor_sync(0xffffffffu, s, o);
        float mu = s * (1.f / 32.f);
        float d  = x - mu;
        float v  = d * d;
#pragma unroll
        for (int o = 16; o; o >>= 1) v += __shfl_xor_sync(0xffffffffu, v, o);
        g_Hemb[(size_t)(r0 + m) * EMB + j] = d * rsqrtf(v * (1.f / 32.f) + 1e-5f) * gj + bj;
    }
}

// ---------------- gi_all: input gates via TRANSPOSED weights (R14 verified) ----------------
__global__ void __launch_bounds__(192, 8)
gi_all(const float* __restrict__ bih) {
    size_t r0 = (size_t)blockIdx.x * INT;
    int j = threadIdx.x;  // output index 0..191
    __shared__ float e_s[INT][EMB];

    for (int t = j; t < INT * EMB; t += 192)
        e_s[t >> 5][t & 31] = g_Hemb[r0 * EMB + t];
    __syncthreads();

    float acc[INT];
    float b = bih[j];
#pragma unroll
    for (int m = 0; m < INT; m++) acc[m] = b;
#pragma unroll
    for (int k = 0; k < EMB; k++) {
        float wv = g_WihT[k * (3 * HIDN) + j];   // coalesced; L1-resident after first iter
#pragma unroll
        for (int m = 0; m < INT; m++) acc[m] += e_s[m][k] * wv;
    }
#pragma unroll
    for (int m = 0; m < INT; m++)
        g_gi[(r0 + m) * 3 * HIDN + j] = acc[m];
}

// ---------------- gruAll: 8 GRU steps, TWO nodes per block (weight-register reuse) ----------------
// grid = NN/2 = 768 blocks, 256 threads. Same (j, k4) layout as the verified R14 kernel;
// each thread's 48 weight registers serve BOTH nodes' FMA phases. Activation on threads
// 0..127 (4 dense warps): nd = tid>>6, u = tid&63. Waves: 768/(148*3) = 1.73 vs R14's 3.46.
__global__ void __launch_bounds__(256, 3)
gruAll(const float* __restrict__ Whh, const float* __restrict__ bhh) {
    __shared__ float h_s[2][HIDN];
    __shared__ float a_s[2][3][HIDN];
    const unsigned full = 0xffffffffu;
    int tid = threadIdx.x;
    int lane = tid & 31, w = tid >> 5;
    int k4 = lane & 3, jq = lane >> 2;
    int j  = w * 8 + jq;
    int kb = k4 * 16;
    int n0 = blockIdx.x * 2;

    // weight registers: 3 gate rows x 16 consecutive k (node-independent!)
    const float4* p0 = (const float4*)(Whh + (size_t)j * HIDN + kb);
    const float4* p1 = (const float4*)(Whh + (size_t)(HIDN + j) * HIDN + kb);
    const float4* p2 = (const float4*)(Whh + (size_t)(2 * HIDN + j) * HIDN + kb);
    float4 w0a = p0[0], w0b = p0[1], w0c = p0[2], w0d = p0[3];
    float4 w1a = p1[0], w1b = p1[1], w1c = p1[2], w1d = p1[3];
    float4 w2a = p2[0], w2b = p2[1], w2c = p2[2], w2d = p2[3];
    float b0 = bhh[j], b1 = bhh[HIDN + j], b2 = bhh[2 * HIDN + j];

    // activation-thread state (threads 0..127): nd = tid>>6, u = tid&63
    int nd = tid >> 6, u = tid & 63;
    float gp0 = 0.f, gp1 = 0.f, gp2 = 0.f;
    if (tid < 2 * HIDN) {
        h_s[nd][u] = 0.f;
        size_t gb = (size_t)(n0 + nd) * 192;
        gp0 = g_gi[gb + u];
        gp1 = g_gi[gb + HIDN + u];
        gp2 = g_gi[gb + 2 * HIDN + u];
    }
    __syncthreads();

    for (int t = 0; t < BS; t++) {
        // ---- FMA phase: both nodes with the same weight registers ----
#pragma unroll
        for (int m = 0; m < 2; m++) {
            float4 hA = *(const float4*)(h_s[m] + kb);
            float4 hB = *(const float4*)(h_s[m] + kb + 4);
            float4 hC = *(const float4*)(h_s[m] + kb + 8);
            float4 hD = *(const float4*)(h_s[m] + kb + 12);
            float a0 = hA.x * w0a.x + hA.y * w0a.y + hA.z * w0a.z + hA.w * w0a.w
                     + hB.x * w0b.x + hB.y * w0b.y + hB.z * w0b.z + hB.w * w0b.w
                     + hC.x * w0c.x + hC.y * w0c.y + hC.z * w0c.z + hC.w * w0c.w
                     + hD.x * w0d.x + hD.y * w0d.y + hD.z * w0d.z + hD.w * w0d.w;
            float a1 = hA.x * w1a.x + hA.y * w1a.y + hA.z * w1a.z + hA.w * w1a.w
                     + hB.x * w1b.x + hB.y * w1b.y + hB.z * w1b.z + hB.w * w1b.w
                     + hC.x * w1c.x + hC.y * w1c.y + hC.z * w1c.z + hC.w * w1c.w
                     + hD.x * w1d.x + hD.y * w1d.y + hD.z * w1d.z + hD.w * w1d.w;
            float a2 = hA.x * w2a.x + hA.y * w2a.y + hA.z * w2a.z + hA.w * w2a.w
                     + hB.x * w2b.x + hB.y * w2b.y + hB.z * w2b.z + hB.w * w2b.w
                     + hC.x * w2c.x + hC.y * w2c.y + hC.z * w2c.z + hC.w * w2c.w
                     + hD.x * w2d.x + hD.y * w2d.y + hD.z * w2d.z + hD.w * w2d.w;
#pragma unroll
            for (int o = 2; o; o >>= 1) {
                a0 += __shfl_xor_sync(full, a0, o);
                a1 += __shfl_xor_sync(full, a1, o);
                a2 += __shfl_xor_sync(full, a2, o);
            }
            if (k4 == 0) {
                a_s[m][0][j] = a0 + b0;
                a_s[m][1][j] = a1 + b1;
                a_s[m][2][j] = a2 + b2;
            }
        }
        __syncthreads();

        // ---- activation phase (4 dense warps: 2 nodes x 64) ----
        if (tid < 2 * HIDN) {
            float r  = sigm(gp0 + a_s[nd][0][u]);
            float z  = sigm(gp1 + a_s[nd][1][u]);
            float nv = tanhf(gp2 + a_s[nd][2][u] * r);
            float hn = (1.f - z) * nv + z * h_s[nd][u];
            h_s[nd][u] = hn;
            g_hall[((size_t)t * NN + n0 + nd) * HIDN + u] = hn;
            if (t < BS - 1) {
                size_t gb = ((size_t)(t + 1) * NN + n0 + nd) * 192;
                gp0 = g_gi[gb + u];
                gp1 = g_gi[gb + HIDN + u];
                gp2 = g_gi[gb + 2 * HIDN + u];
            }
        }
        __syncthreads();
    }
}

// ---------------- post_all: P/Q/xh/a_s/a_d + inits (R14 verified, staged weights) ----------------
__global__ void __launch_bounds__(256, 4)
post_k(const float* __restrict__ Ws1, const float* __restrict__ bs1,
       const float* __restrict__ Wgat,
       const float* __restrict__ asrc, const float* __restrict__ adst,
       const float* __restrict__ bgat,
       float* __restrict__ outp) {
    size_t r0 = (size_t)blockIdx.x * PNT;   // flat (t*NN+n) index
    int tid = threadIdx.x;
    int s = tid >> 6, j = tid & 63;
    __shared__ float Ws1_s[2 * HIDN * HIDN];   // 32 KB
    __shared__ float hn_s[PNT][HIDN];          // 8 KB
    __shared__ float xh_s[PNT][EMB];           // 4 KB

    for (int i = tid; i < 2 * HIDN * HIDN; i += 256) Ws1_s[i] = Ws1[i];
    for (int i = tid; i < PNT * HIDN; i += 256)
        hn_s[i >> 6][i & 63] = g_hall[r0 * HIDN + i];
    __syncthreads();

    const int mb = s * 8;  // row base for this group
    float p[8], q[8];
    float bp = bs1[j];
#pragma unroll
    for (int m = 0; m < 8; m++) { p[m] = bp; q[m] = 0.f; }
#pragma unroll 8
    for (int k = 0; k < HIDN; k++) {
        float w1 = Ws1_s[k * HIDN + j];
        float w2 = Ws1_s[(HIDN + k) * HIDN + j];
#pragma unroll
        for (int m = 0; m < 8; m++) {
            float h = hn_s[mb + m][k];
            p[m] += h * w1; q[m] += h * w2;
        }
    }
#pragma unroll
    for (int m = 0; m < 8; m++) {
        g_P[(r0 + mb + m) * HIDN + j] = p[m];
        g_Q[(r0 + mb + m) * HIDN + j] = q[m];
    }

    if (j < EMB) {
        float x[8];
#pragma unroll
        for (int m = 0; m < 8; m++) x[m] = 0.f;
#pragma unroll 8
        for (int k = 0; k < HIDN; k++) {
            float w = Wgat[k * EMB + j];
#pragma unroll
            for (int m = 0; m < 8; m++) x[m] += hn_s[mb + m][k] * w;
        }
        float bg = bgat[j];
#pragma unroll
        for (int m = 0; m < 8; m++) {
            xh_s[mb + m][j] = x[m];
            g_xh[(r0 + mb + m) * EMB + j] = x[m];
            outp[(r0 + mb + m) * EMB + j] = bg;  // segment_sum init + bias
        }
    }
    __syncthreads();

    if (j < 8 * NH) {
        int m = mb + (j >> 2), h = j & 3;
        float as_ = 0.f, ad_ = 0.f;
#pragma unroll
        for (int c = 0; c < CD; c++) {
            as_ += xh_s[m][h * CD + c] * asrc[h * CD + c];
            ad_ += xh_s[m][h * CD + c] * adst[h * CD + c];
        }
        g_as[(r0 + m) * NH + h]   = as_;
        g_ad[(r0 + m) * NH + h]   = ad_;
        g_ssum[(r0 + m) * NH + h] = 0.f;
    }
}

// ---------------- k2_all: edge scores with COALESCED Q staging (verified R13) ----------------
__global__ void __launch_bounds__(128, 6)
k2_all(const int* __restrict__ dst,
       const float* __restrict__ Ws2, const float* __restrict__ bs2) {
    const unsigned full = 0xffffffffu;
    int warp = threadIdx.x >> 5, lane = threadIdx.x & 31;
    size_t b = (size_t)blockIdx.x * K2W + warp;   // flat (t*NN + n)
    int n = (int)(b % NN);
    size_t tbase = b - n;                          // t*NN

    __shared__ float w2_s[HIDN];
    __shared__ float P_sh[K2W][HIDN];
    __shared__ __align__(16) float q_s[K2W][DEG][68];
    if (threadIdx.x < HIDN) w2_s[threadIdx.x] = Ws2[threadIdx.x];
    P_sh[warp][lane]      = g_P[b * HIDN + lane];
    P_sh[warp][32 + lane] = g_P[b * HIDN + 32 + lane];
    float as0 = g_as[b * NH + 0], as1 = g_as[b * NH + 1];
    float as2 = g_as[b * NH + 2], as3 = g_as[b * NH + 3];
    __syncthreads();

    int d = dst[n * DEG + lane];

    // coalesced staging: row-by-row, float2 per lane
#pragma unroll 8
    for (int r = 0; r < DEG; r++) {
        int dr = __shfl_sync(full, d, r);
        float2 qv = *(const float2*)(g_Q + (tbase + dr) * HIDN + lane * 2);
        *(float2*)(&q_s[warp][r][lane * 2]) = qv;
    }
    __syncwarp();

    // dot over own row (same k-ascending float4 sequence as the verified gather kernel)
    const float* qq = q_s[warp][lane];
    const float* P_s = P_sh[warp];
    float acc = bs2[0];
#pragma unroll
    for (int k4 = 0; k4 < HIDN / 4; k4++) {
        float4 qv = *(const float4*)(qq + k4 * 4);
        int k = k4 * 4;
        acc += fmaxf(P_s[k] + qv.x, 0.f) * w2_s[k]
             + fmaxf(P_s[k + 1] + qv.y, 0.f) * w2_s[k + 1]
             + fmaxf(P_s[k + 2] + qv.z, 0.f) * w2_s[k + 2]
             + fmaxf(P_s[k + 3] + qv.w, 0.f) * w2_s[k + 3];
    }
    float score = sigm(acc);

    // top-k (k=4) among 32 lanes; ties -> lower index (matches jax.lax.top_k)
    bool sel = false;
#pragma unroll
    for (int r = 0; r < KS; r++) {
        float v = sel ? -1e30f : score;
        int   idx = lane;
#pragma unroll
        for (int o = 16; o; o >>= 1) {
            float ov = __shfl_xor_sync(full, v, o);
            int   oi = __shfl_xor_sync(full, idx, o);
            if (ov > v || (ov == v && oi < idx)) { v = ov; idx = oi; }
        }
        if (lane == idx) sel = true;
    }
    unsigned ball = __ballot_sync(full, sel);
    if (sel) {
        int slot = __popc(ball & ((1u << lane) - 1u));
        g_kdst[b * KS + slot] = d;
        g_kw[b * KS + slot]   = score;
        float4 adv = *(const float4*)(g_ad + (tbase + d) * NH);
        float4 ex4;
        float lg;
        lg = as0 + adv.x; lg = lg > 0.f ? lg : 0.2f * lg; ex4.x = expf(lg);
        lg = as1 + adv.y; lg = lg > 0.f ? lg : 0.2f * lg; ex4.y = expf(lg);
        lg = as2 + adv.z; lg = lg > 0.f ? lg : 0.2f * lg; ex4.z = expf(lg);
        lg = as3 + adv.w; lg = lg > 0.f ? lg : 0.2f * lg; ex4.w = expf(lg);
        *(float4*)(g_kex + (b * KS + slot) * NH) = ex4;
        float* ss = g_ssum + (tbase + d) * NH;
        atomicAdd(ss + 0, ex4.x);
        atomicAdd(ss + 1, ex4.y);
        atomicAdd(ss + 2, ex4.z);
        atomicAdd(ss + 3, ex4.w);
    }
}

// ---------------- k4_all: alpha + row-normalize + dedup + out messages ----------------
__global__ void __launch_bounds__(256, 8)
k4_all(float* __restrict__ outp) {
    int warp = threadIdx.x >> 5, lane = threadIdx.x & 31;
    size_t b = (size_t)blockIdx.x * 8 + warp;   // flat (t*NN + n)
    int n = (int)(b % NN);
    size_t tbase = b - n;                        // t*NN
    const unsigned full = 0xffffffffu;
    int i = (lane >> 2) & 3, h = lane & 3;       // lanes 16..31 mirror 0..15

    int   d_i = g_kdst[b * KS + i];
    float w_i = g_kw[b * KS + i];
    float ex  = g_kex[(b * KS + i) * NH + h];
    float alpha = ex / fmaxf(g_ssum[(tbase + d_i) * NH + h], 1e-16f);

    float rs = alpha;
    rs += __shfl_xor_sync(full, rs, 4);
    rs += __shfl_xor_sync(full, rs, 8);
    float rinv = 1.f / fmaxf(rs, 1e-9f);

    bool first = true;
    float acc = alpha;
#pragma unroll
    for (int jj = 0; jj < KS; jj++) {
        int   dj = __shfl_sync(full, d_i,   jj * 4 + h);
        float aj = __shfl_sync(full, alpha, jj * 4 + h);
        if (jj < i && dj == d_i) first = false;
        if (jj > i && dj == d_i) acc += aj;
    }
    if (lane < 16) {
        g_Aval[(b * KS + i) * NH + h] = first ? acc * rinv : 0.f;
        if (h == 0) g_Adst[b * KS + i] = first ? d_i : -1;
    }

    int h2 = lane >> 3, c = lane & 7;
    float xhv = g_xh[b * EMB + h2 * CD + c];
#pragma unroll
    for (int jj = 0; jj < KS; jj++) {
        float a_jh = __shfl_sync(full, alpha, jj * 4 + h2);
        float wj   = __shfl_sync(full, w_i,   jj * 4);
        int   dj   = __shfl_sync(full, d_i,   jj * 4);
        atomicAdd(&outp[(tbase + dj) * EMB + h2 * CD + c], a_jh * xhv * wj);
    }
}

// ---------------- scatterA: write the nonzero attention entries ----------------
__global__ void scatterA(float* __restrict__ outp) {
    int gid = blockIdx.x * blockDim.x + threadIdx.x;
    if (gid >= BS * NN * KS) return;
    int slot = gid & 3;
    size_t b = gid >> 2;          // t*NN + n
    int n = (int)(b % NN);
    int t = (int)(b / NN);
    int d = g_Adst[b * KS + slot];
    if (d < 0) return;
    float4 v = *(const float4*)(g_Aval + (b * KS + slot) * NH);
    float* Abase = outp + ATTN_OFS;
    size_t rowstride = (size_t)NN * NN;
    size_t base = ((size_t)t * NH) * rowstride + (size_t)n * NN + d;
    Abase[base]                 = v.x;
    Abase[base + rowstride]     = v.y;
    Abase[base + 2 * rowstride] = v.z;
    Abase[base + 3 * rowstride] = v.w;
}

// ---------------- launch (single stream) ----------------
extern "C" void kernel_launch(void* const* d_in, const int* in_sizes, int n_in,
                              void* d_out, int out_size) {
    int base = (in_sizes[3] == 1) ? 4 : 3;  // scalar k may or may not be materialized
    const float* Ht  = (const float*)d_in[0];
    const int*   dst = (const int*)d_in[2];
    const float* We1 = (const float*)d_in[base + 0];
    const float* be1 = (const float*)d_in[base + 1];
    const float* We2 = (const float*)d_in[base + 2];
    const float* be2 = (const float*)d_in[base + 3];
    const float* lng = (const float*)d_in[base + 4];
    const float* lnb = (const float*)d_in[base + 5];
    const float* Wih = (const float*)d_in[base + 6];
    const float* Whh = (const float*)d_in[base + 7];
    const float* bih = (const float*)d_in[base + 8];
    const float* bhh = (const float*)d_in[base + 9];
    const float* Ws1 = (const float*)d_in[base + 10];
    const float* bs1 = (const float*)d_in[base + 11];
    const float* Ws2 = (const float*)d_in[base + 12];
    const float* bs2 = (const float*)d_in[base + 13];
    const float* Wgat = (const float*)d_in[base + 14];
    const float* asrc = (const float*)d_in[base + 15];
    const float* adst = (const float*)d_in[base + 16];
    const float* bgat = (const float*)d_in[base + 17];
    float* outp = (float*)d_out;

    zeroA<<<4608, 256>>>(outp);
    transWih<<<(3 * HIDN * EMB + 255) / 256, 256>>>(Wih);
    embed_k<<<(BS * NN) / RTB, 32>>>(Ht, We1, be1, We2, be2, lng, lnb);
    gi_all<<<(BS * NN) / INT, 192>>>(bih);
    gruAll<<<NN / 2, 256>>>(Whh, bhh);
    post_k<<<(BS * NN) / PNT, 256>>>(Ws1, bs1, Wgat, asrc, adst, bgat, outp);
    k2_all<<<(BS * NN) / K2W, 128>>>(dst, Ws2, bs2);
    k4_all<<<(BS * NN) / 8, 256>>>(outp);
    scatterA<<<(BS * NN * KS + 255) / 256, 256>>>(outp);
}

// round 17
// speedup vs baseline: 1.2196x; 1.0364x over previous
#include <cuda_runtime.h>
#include <math.h>

// Problem constants (fixed by the reference)
#define NN    1536   // nodes
#define DEG   32     // candidate out-degree per node
#define BS    8      // sequential batch steps
#define OBSD  33
#define HIDN  64
#define NH    4      // heads
#define CD    8      // channels per head
#define KS    4      // top-k
#define EMB   32
#define ATTN_OFS ((size_t)BS * NN * EMB)   // outs precede attns in d_out

#define RTB 8    // rows per block in embed
#define INT 8    // rows per block in gi_all
#define PNT 32   // (t,node) pairs per block in post (4 groups x 8)
#define K2W 4    // warps per block in k2
#define GRN 4    // nodes per block in gruAll

// -------- persistent device scratch (no allocations allowed) --------
__device__ float g_Hemb[BS * NN * EMB];
__device__ float g_WihT[EMB * 3 * HIDN];     // transposed Wih: [k][o]
__device__ float g_gi[BS * NN * 3 * HIDN];   // input-side GRU gates (batched)
__device__ float g_hall[BS * NN * HIDN];
__device__ float g_P[BS * NN * HIDN];
__device__ float g_Q[BS * NN * HIDN];
__device__ float g_xh[BS * NN * EMB];
__device__ float g_as[BS * NN * NH];
__device__ float g_ad[BS * NN * NH];
__device__ int   g_kdst[BS * NN * KS];
__device__ float g_kw[BS * NN * KS];
__device__ float g_kex[BS * NN * KS * NH];
__device__ float g_ssum[BS * NN * NH];
__device__ float g_Aval[BS * NN * KS * NH];  // normalized, dedup-merged A entries
__device__ int   g_Adst[BS * NN * KS];       // -1 = duplicate slot (skip)

__device__ __forceinline__ float sigm(float x) { return 1.f / (1.f + expf(-x)); }

// ---------------- zero-fill the whole attention output region (DRAM-floor kernel) ----------------
__global__ void zeroA(float* __restrict__ outp) {
    float4* base = (float4*)(outp + ATTN_OFS);
    size_t total = (size_t)BS * NH * NN * NN / 4;
    size_t stride = (size_t)gridDim.x * blockDim.x;
    float4 z = make_float4(0.f, 0.f, 0.f, 0.f);
    for (size_t i = (size_t)blockIdx.x * blockDim.x + threadIdx.x; i < total; i += stride)
        base[i] = z;
}

// ---------------- transWih: Wih[o][k] -> WihT[k][o] (one-time, tiny) ----------------
__global__ void transWih(const float* __restrict__ Wih) {
    int i = blockIdx.x * 256 + threadIdx.x;      // 6144 elements
    if (i < 3 * HIDN * EMB) {
        int o = i >> 5, k = i & 31;
        g_WihT[k * (3 * HIDN) + o] = Wih[i];
    }
}

// ---------------- Obs embedding: Linear-ReLU-Linear-ReLU-LayerNorm (R14 verified) ----------------
__global__ void __launch_bounds__(32, 16)
embed_k(const float* __restrict__ Ht,
        const float* __restrict__ We1, const float* __restrict__ be1,
        const float* __restrict__ We2, const float* __restrict__ be2,
        const float* __restrict__ lng, const float* __restrict__ lnb) {
    int r0 = blockIdx.x * RTB;
    int j  = threadIdx.x;  // 0..31
    __shared__ float in_s[RTB][OBSD + 1];
    __shared__ float x1_s[RTB][EMB];

    for (int t = j; t < RTB * OBSD; t += 32)
        in_s[t / OBSD][t % OBSD] = Ht[(size_t)r0 * OBSD + t];
    __syncwarp();

    float a[RTB];
    float b1 = be1[j];
#pragma unroll
    for (int m = 0; m < RTB; m++) a[m] = b1;
#pragma unroll
    for (int k = 0; k < OBSD; k++) {
        float w = We1[k * EMB + j];
#pragma unroll
        for (int m = 0; m < RTB; m++) a[m] += in_s[m][k] * w;
    }
#pragma unroll
    for (int m = 0; m < RTB; m++) x1_s[m][j] = fmaxf(a[m], 0.f);
    __syncwarp();

    float b[RTB];
    float b2 = be2[j];
#pragma unroll
    for (int m = 0; m < RTB; m++) b[m] = b2;
#pragma unroll
    for (int k = 0; k < EMB; k++) {
        float w = We2[k * EMB + j];
#pragma unroll
        for (int m = 0; m < RTB; m++) b[m] += x1_s[m][k] * w;
    }

    float gj = lng[j], bj = lnb[j];
#pragma unroll
    for (int m = 0; m < RTB; m++) {
        float x = fmaxf(b[m], 0.f);
        float s = x;
#pragma unroll
        for (int o = 16; o; o >>= 1) s += __shfl_xor_sync(0xffffffffu, s, o);
        float mu = s * (1.f / 32.f);
        float d  = x - mu;
        float v  = d * d;
#pragma unroll
        for (int o = 16; o; o >>= 1) v += __shfl_xor_sync(0xffffffffu, v, o);
        g_Hemb[(size_t)(r0 + m) * EMB + j] = d * rsqrtf(v * (1.f / 32.f) + 1e-5f) * gj + bj;
    }
}

// ---------------- gi_all: input gates via TRANSPOSED weights (R14 verified) ----------------
__global__ void __launch_bounds__(192, 8)
gi_all(const float* __restrict__ bih) {
    size_t r0 = (size_t)blockIdx.x * INT;
    int j = threadIdx.x;  // output index 0..191
    __shared__ float e_s[INT][EMB];

    for (int t = j; t < INT * EMB; t += 192)
        e_s[t >> 5][t & 31] = g_Hemb[r0 * EMB + t];
    __syncthreads();

    float acc[INT];
    float b = bih[j];
#pragma unroll
    for (int m = 0; m < INT; m++) acc[m] = b;
#pragma unroll
    for (int k = 0; k < EMB; k++) {
        float wv = g_WihT[k * (3 * HIDN) + j];   // coalesced; L1-resident after first iter
#pragma unroll
        for (int m = 0; m < INT; m++) acc[m] += e_s[m][k] * wv;
    }
#pragma unroll
    for (int m = 0; m < INT; m++)
        g_gi[(r0 + m) * 3 * HIDN + j] = acc[m];
}

// ---------------- gruAll: 8 GRU steps, FOUR nodes per block (weight-register reuse, 1 wave) ----------------
// grid = NN/4 = 384 blocks, 256 threads. Same (j, k4) layout as the verified R14/R16 kernels;
// each thread's 48 weight registers serve all 4 nodes' FMA phases. Activation fully dense
// (all 256 threads: nd = tid>>6, u = tid&63). 384 blocks @ 3/SM = 0.86 waves.
__global__ void __launch_bounds__(256, 3)
gruAll(const float* __restrict__ Whh, const float* __restrict__ bhh) {
    __shared__ float h_s[GRN][HIDN];
    __shared__ float a_s[GRN][3][HIDN];
    const unsigned full = 0xffffffffu;
    int tid = threadIdx.x;
    int lane = tid & 31, w = tid >> 5;
    int k4 = lane & 3, jq = lane >> 2;
    int j  = w * 8 + jq;
    int kb = k4 * 16;
    int n0 = blockIdx.x * GRN;

    // weight registers: 3 gate rows x 16 consecutive k (node-independent)
    const float4* p0 = (const float4*)(Whh + (size_t)j * HIDN + kb);
    const float4* p1 = (const float4*)(Whh + (size_t)(HIDN + j) * HIDN + kb);
    const float4* p2 = (const float4*)(Whh + (size_t)(2 * HIDN + j) * HIDN + kb);
    float4 w0a = p0[0], w0b = p0[1], w0c = p0[2], w0d = p0[3];
    float4 w1a = p1[0], w1b = p1[1], w1c = p1[2], w1d = p1[3];
    float4 w2a = p2[0], w2b = p2[1], w2c = p2[2], w2d = p2[3];
    float b0 = bhh[j], b1 = bhh[HIDN + j], b2 = bhh[2 * HIDN + j];

    // activation-thread state (ALL 256 threads dense): nd = tid>>6, u = tid&63
    int nd = tid >> 6, u = tid & 63;
    h_s[nd][u] = 0.f;
    size_t gb = (size_t)(n0 + nd) * 192;
    float gp0 = g_gi[gb + u];
    float gp1 = g_gi[gb + HIDN + u];
    float gp2 = g_gi[gb + 2 * HIDN + u];
    __syncthreads();

    for (int t = 0; t < BS; t++) {
        // ---- FMA phase: all 4 nodes with the same weight registers ----
#pragma unroll
        for (int m = 0; m < GRN; m++) {
            float4 hA = *(const float4*)(h_s[m] + kb);
            float4 hB = *(const float4*)(h_s[m] + kb + 4);
            float4 hC = *(const float4*)(h_s[m] + kb + 8);
            float4 hD = *(const float4*)(h_s[m] + kb + 12);
            float a0 = hA.x * w0a.x + hA.y * w0a.y + hA.z * w0a.z + hA.w * w0a.w
                     + hB.x * w0b.x + hB.y * w0b.y + hB.z * w0b.z + hB.w * w0b.w
                     + hC.x * w0c.x + hC.y * w0c.y + hC.z * w0c.z + hC.w * w0c.w
                     + hD.x * w0d.x + hD.y * w0d.y + hD.z * w0d.z + hD.w * w0d.w;
            float a1 = hA.x * w1a.x + hA.y * w1a.y + hA.z * w1a.z + hA.w * w1a.w
                     + hB.x * w1b.x + hB.y * w1b.y + hB.z * w1b.z + hB.w * w1b.w
                     + hC.x * w1c.x + hC.y * w1c.y + hC.z * w1c.z + hC.w * w1c.w
                     + hD.x * w1d.x + hD.y * w1d.y + hD.z * w1d.z + hD.w * w1d.w;
            float a2 = hA.x * w2a.x + hA.y * w2a.y + hA.z * w2a.z + hA.w * w2a.w
                     + hB.x * w2b.x + hB.y * w2b.y + hB.z * w2b.z + hB.w * w2b.w
                     + hC.x * w2c.x + hC.y * w2c.y + hC.z * w2c.z + hC.w * w2c.w
                     + hD.x * w2d.x + hD.y * w2d.y + hD.z * w2d.z + hD.w * w2d.w;
#pragma unroll
            for (int o = 2; o; o >>= 1) {
                a0 += __shfl_xor_sync(full, a0, o);
                a1 += __shfl_xor_sync(full, a1, o);
                a2 += __shfl_xor_sync(full, a2, o);
            }
            if (k4 == 0) {
                a_s[m][0][j] = a0 + b0;
                a_s[m][1][j] = a1 + b1;
                a_s[m][2][j] = a2 + b2;
            }
        }
        __syncthreads();

        // ---- activation phase (all 8 warps dense: 4 nodes x 64) ----
        {
            float r  = sigm(gp0 + a_s[nd][0][u]);
            float z  = sigm(gp1 + a_s[nd][1][u]);
            float nv = tanhf(gp2 + a_s[nd][2][u] * r);
            float hn = (1.f - z) * nv + z * h_s[nd][u];
            h_s[nd][u] = hn;
            g_hall[((size_t)t * NN + n0 + nd) * HIDN + u] = hn;
            if (t < BS - 1) {
                size_t gb2 = ((size_t)(t + 1) * NN + n0 + nd) * 192;
                gp0 = g_gi[gb2 + u];
                gp1 = g_gi[gb2 + HIDN + u];
                gp2 = g_gi[gb2 + 2 * HIDN + u];
            }
        }
        __syncthreads();
    }
}

// ---------------- post_all: P/Q/xh/a_s/a_d + inits (R14 verified, staged weights) ----------------
__global__ void __launch_bounds__(256, 4)
post_k(const float* __restrict__ Ws1, const float* __restrict__ bs1,
       const float* __restrict__ Wgat,
       const float* __restrict__ asrc, const float* __restrict__ adst,
       const float* __restrict__ bgat,
       float* __restrict__ outp) {
    size_t r0 = (size_t)blockIdx.x * PNT;   // flat (t*NN+n) index
    int tid = threadIdx.x;
    int s = tid >> 6, j = tid & 63;
    __shared__ float Ws1_s[2 * HIDN * HIDN];   // 32 KB
    __shared__ float hn_s[PNT][HIDN];          // 8 KB
    __shared__ float xh_s[PNT][EMB];           // 4 KB

    for (int i = tid; i < 2 * HIDN * HIDN; i += 256) Ws1_s[i] = Ws1[i];
    for (int i = tid; i < PNT * HIDN; i += 256)
        hn_s[i >> 6][i & 63] = g_hall[r0 * HIDN + i];
    __syncthreads();

    const int mb = s * 8;  // row base for this group
    float p[8], q[8];
    float bp = bs1[j];
#pragma unroll
    for (int m = 0; m < 8; m++) { p[m] = bp; q[m] = 0.f; }
#pragma unroll 8
    for (int k = 0; k < HIDN; k++) {
        float w1 = Ws1_s[k * HIDN + j];
        float w2 = Ws1_s[(HIDN + k) * HIDN + j];
#pragma unroll
        for (int m = 0; m < 8; m++) {
            float h = hn_s[mb + m][k];
            p[m] += h * w1; q[m] += h * w2;
        }
    }
#pragma unroll
    for (int m = 0; m < 8; m++) {
        g_P[(r0 + mb + m) * HIDN + j] = p[m];
        g_Q[(r0 + mb + m) * HIDN + j] = q[m];
    }

    if (j < EMB) {
        float x[8];
#pragma unroll
        for (int m = 0; m < 8; m++) x[m] = 0.f;
#pragma unroll 8
        for (int k = 0; k < HIDN; k++) {
            float w = Wgat[k * EMB + j];
#pragma unroll
            for (int m = 0; m < 8; m++) x[m] += hn_s[mb + m][k] * w;
        }
        float bg = bgat[j];
#pragma unroll
        for (int m = 0; m < 8; m++) {
            xh_s[mb + m][j] = x[m];
            g_xh[(r0 + mb + m) * EMB + j] = x[m];
            outp[(r0 + mb + m) * EMB + j] = bg;  // segment_sum init + bias
        }
    }
    __syncthreads();

    if (j < 8 * NH) {
        int m = mb + (j >> 2), h = j & 3;
        float as_ = 0.f, ad_ = 0.f;
#pragma unroll
        for (int c = 0; c < CD; c++) {
            as_ += xh_s[m][h * CD + c] * asrc[h * CD + c];
            ad_ += xh_s[m][h * CD + c] * adst[h * CD + c];
        }
        g_as[(r0 + m) * NH + h]   = as_;
        g_ad[(r0 + m) * NH + h]   = ad_;
        g_ssum[(r0 + m) * NH + h] = 0.f;
    }
}

// ---------------- k2_all: edge scores with COALESCED Q staging (verified R13) ----------------
__global__ void __launch_bounds__(128, 6)
k2_all(const int* __restrict__ dst,
       const float* __restrict__ Ws2, const float* __restrict__ bs2) {
    const unsigned full = 0xffffffffu;
    int warp = threadIdx.x >> 5, lane = threadIdx.x & 31;
    size_t b = (size_t)blockIdx.x * K2W + warp;   // flat (t*NN + n)
    int n = (int)(b % NN);
    size_t tbase = b - n;                          // t*NN

    __shared__ float w2_s[HIDN];
    __shared__ float P_sh[K2W][HIDN];
    __shared__ __align__(16) float q_s[K2W][DEG][68];
    if (threadIdx.x < HIDN) w2_s[threadIdx.x] = Ws2[threadIdx.x];
    P_sh[warp][lane]      = g_P[b * HIDN + lane];
    P_sh[warp][32 + lane] = g_P[b * HIDN + 32 + lane];
    float as0 = g_as[b * NH + 0], as1 = g_as[b * NH + 1];
    float as2 = g_as[b * NH + 2], as3 = g_as[b * NH + 3];
    __syncthreads();

    int d = dst[n * DEG + lane];

    // coalesced staging: row-by-row, float2 per lane
#pragma unroll 8
    for (int r = 0; r < DEG; r++) {
        int dr = __shfl_sync(full, d, r);
        float2 qv = *(const float2*)(g_Q + (tbase + dr) * HIDN + lane * 2);
        *(float2*)(&q_s[warp][r][lane * 2]) = qv;
    }
    __syncwarp();

    // dot over own row (same k-ascending float4 sequence as the verified gather kernel)
    const float* qq = q_s[warp][lane];
    const float* P_s = P_sh[warp];
    float acc = bs2[0];
#pragma unroll
    for (int k4 = 0; k4 < HIDN / 4; k4++) {
        float4 qv = *(const float4*)(qq + k4 * 4);
        int k = k4 * 4;
        acc += fmaxf(P_s[k] + qv.x, 0.f) * w2_s[k]
             + fmaxf(P_s[k + 1] + qv.y, 0.f) * w2_s[k + 1]
             + fmaxf(P_s[k + 2] + qv.z, 0.f) * w2_s[k + 2]
             + fmaxf(P_s[k + 3] + qv.w, 0.f) * w2_s[k + 3];
    }
    float score = sigm(acc);

    // top-k (k=4) among 32 lanes; ties -> lower index (matches jax.lax.top_k)
    bool sel = false;
#pragma unroll
    for (int r = 0; r < KS; r++) {
        float v = sel ? -1e30f : score;
        int   idx = lane;
#pragma unroll
        for (int o = 16; o; o >>= 1) {
            float ov = __shfl_xor_sync(full, v, o);
            int   oi = __shfl_xor_sync(full, idx, o);
            if (ov > v || (ov == v && oi < idx)) { v = ov; idx = oi; }
        }
        if (lane == idx) sel = true;
    }
    unsigned ball = __ballot_sync(full, sel);
    if (sel) {
        int slot = __popc(ball & ((1u << lane) - 1u));
        g_kdst[b * KS + slot] = d;
        g_kw[b * KS + slot]   = score;
        float4 adv = *(const float4*)(g_ad + (tbase + d) * NH);
        float4 ex4;
        float lg;
        lg = as0 + adv.x; lg = lg > 0.f ? lg : 0.2f * lg; ex4.x = expf(lg);
        lg = as1 + adv.y; lg = lg > 0.f ? lg : 0.2f * lg; ex4.y = expf(lg);
        lg = as2 + adv.z; lg = lg > 0.f ? lg : 0.2f * lg; ex4.z = expf(lg);
        lg = as3 + adv.w; lg = lg > 0.f ? lg : 0.2f * lg; ex4.w = expf(lg);
        *(float4*)(g_kex + (b * KS + slot) * NH) = ex4;
        float* ss = g_ssum + (tbase + d) * NH;
        atomicAdd(ss + 0, ex4.x);
        atomicAdd(ss + 1, ex4.y);
        atomicAdd(ss + 2, ex4.z);
        atomicAdd(ss + 3, ex4.w);
    }
}

// ---------------- k4_all: alpha + row-normalize + dedup + out messages ----------------
__global__ void __launch_bounds__(256, 8)
k4_all(float* __restrict__ outp) {
    int warp = threadIdx.x >> 5, lane = threadIdx.x & 31;
    size_t b = (size_t)blockIdx.x * 8 + warp;   // flat (t*NN + n)
    int n = (int)(b % NN);
    size_t tbase = b - n;                        // t*NN
    const unsigned full = 0xffffffffu;
    int i = (lane >> 2) & 3, h = lane & 3;       // lanes 16..31 mirror 0..15

    int   d_i = g_kdst[b * KS + i];
    float w_i = g_kw[b * KS + i];
    float ex  = g_kex[(b * KS + i) * NH + h];
    float alpha = ex / fmaxf(g_ssum[(tbase + d_i) * NH + h], 1e-16f);

    float rs = alpha;
    rs += __shfl_xor_sync(full, rs, 4);
    rs += __shfl_xor_sync(full, rs, 8);
    float rinv = 1.f / fmaxf(rs, 1e-9f);

    bool first = true;
    float acc = alpha;
#pragma unroll
    for (int jj = 0; jj < KS; jj++) {
        int   dj = __shfl_sync(full, d_i,   jj * 4 + h);
        float aj = __shfl_sync(full, alpha, jj * 4 + h);
        if (jj < i && dj == d_i) first = false;
        if (jj > i && dj == d_i) acc += aj;
    }
    if (lane < 16) {
        g_Aval[(b * KS + i) * NH + h] = first ? acc * rinv : 0.f;
        if (h == 0) g_Adst[b * KS + i] = first ? d_i : -1;
    }

    int h2 = lane >> 3, c = lane & 7;
    float xhv = g_xh[b * EMB + h2 * CD + c];
#pragma unroll
    for (int jj = 0; jj < KS; jj++) {
        float a_jh = __shfl_sync(full, alpha, jj * 4 + h2);
        float wj   = __shfl_sync(full, w_i,   jj * 4);
        int   dj   = __shfl_sync(full, d_i,   jj * 4);
        atomicAdd(&outp[(tbase + dj) * EMB + h2 * CD + c], a_jh * xhv * wj);
    }
}

// ---------------- scatterA: write the nonzero attention entries ----------------
__global__ void scatterA(float* __restrict__ outp) {
    int gid = blockIdx.x * blockDim.x + threadIdx.x;
    if (gid >= BS * NN * KS) return;
    int slot = gid & 3;
    size_t b = gid >> 2;          // t*NN + n
    int n = (int)(b % NN);
    int t = (int)(b / NN);
    int d = g_Adst[b * KS + slot];
    if (d < 0) return;
    float4 v = *(const float4*)(g_Aval + (b * KS + slot) * NH);
    float* Abase = outp + ATTN_OFS;
    size_t rowstride = (size_t)NN * NN;
    size_t base = ((size_t)t * NH) * rowstride + (size_t)n * NN + d;
    Abase[base]                 = v.x;
    Abase[base + rowstride]     = v.y;
    Abase[base + 2 * rowstride] = v.z;
    Abase[base + 3 * rowstride] = v.w;
}

// ---------------- launch (single stream) ----------------
extern "C" void kernel_launch(void* const* d_in, const int* in_sizes, int n_in,
                              void* d_out, int out_size) {
    int base = (in_sizes[3] == 1) ? 4 : 3;  // scalar k may or may not be materialized
    const float* Ht  = (const float*)d_in[0];
    const int*   dst = (const int*)d_in[2];
    const float* We1 = (const float*)d_in[base + 0];
    const float* be1 = (const float*)d_in[base + 1];
    const float* We2 = (const float*)d_in[base + 2];
    const float* be2 = (const float*)d_in[base + 3];
    const float* lng = (const float*)d_in[base + 4];
    const float* lnb = (const float*)d_in[base + 5];
    const float* Wih = (const float*)d_in[base + 6];
    const float* Whh = (const float*)d_in[base + 7];
    const float* bih = (const float*)d_in[base + 8];
    const float* bhh = (const float*)d_in[base + 9];
    const float* Ws1 = (const float*)d_in[base + 10];
    const float* bs1 = (const float*)d_in[base + 11];
    const float* Ws2 = (const float*)d_in[base + 12];
    const float* bs2 = (const float*)d_in[base + 13];
    const float* Wgat = (const float*)d_in[base + 14];
    const float* asrc = (const float*)d_in[base + 15];
    const float* adst = (const float*)d_in[base + 16];
    const float* bgat = (const float*)d_in[base + 17];
    float* outp = (float*)d_out;

    zeroA<<<4608, 256>>>(outp);
    transWih<<<(3 * HIDN * EMB + 255) / 256, 256>>>(Wih);
    embed_k<<<(BS * NN) / RTB, 32>>>(Ht, We1, be1, We2, be2, lng, lnb);
    gi_all<<<(BS * NN) / INT, 192>>>(bih);
    gruAll<<<NN / GRN, 256>>>(Whh, bhh);
    post_k<<<(BS * NN) / PNT, 256>>>(Ws1, bs1, Wgat, asrc, adst, bgat, outp);
    k2_all<<<(BS * NN) / K2W, 128>>>(dst, Ws2, bs2);
    k4_all<<<(BS * NN) / 8, 256>>>(outp);
    scatterA<<<(BS * NN * KS + 255) / 256, 256>>>(outp);
}